// round 4
// baseline (speedup 1.0000x reference)
#include <cuda_runtime.h>
#include <math_constants.h>

// x [B=64, C=512, H=28, W=28] fp32; cc [B,28,28] bool widened to int32.
// out [B, 2C]: out[b,c]   = (sum_hw x[b,c,hw]*cc[b,hw] + x[b,c,0]) / max(cnt_b,1)
//              out[b,C+c] = max_hw x[b,c,hw]
//
// CTA = 8 channels of one batch (grid 4096, 256 thr, warp-per-row).
// Load-first: each lane issues its 7 x float4 LDGs up front (MLP=7); the
// mask int4 load/convert/store overlaps that latency; ONE barrier; then
// FMA-consume with smem mask. Count is re-accumulated per warp during the
// consume loop (each warp reads the full mask anyway) -> no block reduce.

#define HW   784
#define HW4  196
#define C_DIM 512
#define THREADS 256
#define ROWS_PER_CTA 8

__global__ __launch_bounds__(THREADS) void pool_kernel(
    const float* __restrict__ x,
    const int* __restrict__ cc,
    float* __restrict__ out)
{
    __shared__ float s_m[HW];   // float mask for this batch

    const int tid  = threadIdx.x;
    const int wid  = tid >> 5;
    const int lane = tid & 31;

    const int bc0 = blockIdx.x * ROWS_PER_CTA;
    const int b   = bc0 >> 9;
    const int bc  = bc0 + wid;

    const float4* __restrict__ xr = reinterpret_cast<const float4*>(x + (size_t)bc * HW);

    // ---- 1. Issue all x loads first (196 = 6*32 + 4) ----
    float4 v[7];
    #pragma unroll
    for (int j = 0; j < 6; j++) v[j] = xr[lane + 32 * j];
    const bool tail = (lane < 4);
    if (tail) v[6] = xr[lane + 192];

    // ---- 2. Mask -> smem float (overlaps x-load latency) ----
    if (tid < HW4) {
        int4 m = reinterpret_cast<const int4*>(cc + (size_t)b * HW)[tid];
        float4 f;
        f.x = m.x ? 1.0f : 0.0f;
        f.y = m.y ? 1.0f : 0.0f;
        f.z = m.z ? 1.0f : 0.0f;
        f.w = m.w ? 1.0f : 0.0f;
        *reinterpret_cast<float4*>(&s_m[4 * tid]) = f;
    }
    __syncthreads();

    // ---- 3. Consume: FMA with mask, count, max ----
    const float4* __restrict__ mm = reinterpret_cast<const float4*>(s_m);
    float sum0 = 0.0f, sum1 = 0.0f;
    float cnt  = 0.0f;
    float mx   = -CUDART_INF_F;

    #pragma unroll
    for (int j = 0; j < 6; j++) {
        float4 f = mm[lane + 32 * j];
        sum0 = fmaf(v[j].x, f.x, fmaf(v[j].y, f.y, sum0));
        sum1 = fmaf(v[j].z, f.z, fmaf(v[j].w, f.w, sum1));
        cnt += (f.x + f.y) + (f.z + f.w);
        mx = fmaxf(mx, fmaxf(fmaxf(v[j].x, v[j].y), fmaxf(v[j].z, v[j].w)));
    }
    if (tail) {
        float4 f = mm[lane + 192];
        sum0 = fmaf(v[6].x, f.x, fmaf(v[6].y, f.y, sum0));
        sum1 = fmaf(v[6].z, f.z, fmaf(v[6].w, f.w, sum1));
        cnt += (f.x + f.y) + (f.z + f.w);
        mx = fmaxf(mx, fmaxf(fmaxf(v[6].x, v[6].y), fmaxf(v[6].z, v[6].w)));
    }

    float sum = sum0 + sum1;
    #pragma unroll
    for (int off = 16; off > 0; off >>= 1) {
        sum += __shfl_down_sync(0xffffffffu, sum, off);
        cnt += __shfl_down_sync(0xffffffffu, cnt, off);
        mx   = fmaxf(mx, __shfl_down_sync(0xffffffffu, mx, off));
    }

    if (lane == 0) {
        const int c = bc & (C_DIM - 1);
        sum += v[0].x;                       // the + x[b,c,0,0] quirk: already in regs
        float denom = (cnt == 0.0f) ? 1.0f : cnt;
        out[(size_t)b * (2 * C_DIM) + c]         = sum / denom;
        out[(size_t)b * (2 * C_DIM) + C_DIM + c] = mx;
    }
}

extern "C" void kernel_launch(void* const* d_in, const int* in_sizes, int n_in,
                              void* d_out, int out_size)
{
    const float* x  = (const float*)d_in[0];
    const int*   cc = (const int*)d_in[1];
    float*       o  = (float*)d_out;

    pool_kernel<<<(64 * C_DIM) / ROWS_PER_CTA, THREADS>>>(x, cc, o);
}